// round 16
// baseline (speedup 1.0000x reference)
#include <cuda_runtime.h>
#include <cuda_bf16.h>
#include <math.h>

#define D_MODEL 1024
#define D_KEY   128
#define N_SUB   256
#define TOPK    8
#define MAXNT   8192
#define SC_LD   260

// -------- scratch (device globals) --------
__device__ __align__(128) __nv_bfloat16 g_xb [MAXNT * D_MODEL];
__device__ __align__(128) __nv_bfloat16 g_wqb[2 * D_KEY * D_MODEL];
__device__ __align__(128) __nv_bfloat16 g_kb [2 * N_SUB * D_KEY];
__device__ __align__(128) unsigned g_cand[MAXNT * 16];

// ================= base-PTX helpers =================
__device__ __forceinline__ unsigned smem_u32(const void* p) {
    unsigned a;
    asm("{ .reg .u64 t; cvta.to.shared.u64 t, %1; cvt.u32.u64 %0, t; }" : "=r"(a) : "l"(p));
    return a;
}
__device__ __forceinline__ void cpa16(unsigned d, const void* s) {
    asm volatile("cp.async.cg.shared.global [%0], [%1], 16;" :: "r"(d), "l"(s));
}
__device__ __forceinline__ void cpcommit() { asm volatile("cp.async.commit_group;" ::: "memory"); }
template<int N> __device__ __forceinline__ void cpwait() {
    asm volatile("cp.async.wait_group %0;" :: "n"(N) : "memory");
}
__device__ __forceinline__ void ldsm4(unsigned addr, unsigned& r0, unsigned& r1,
                                      unsigned& r2, unsigned& r3) {
    asm volatile("ldmatrix.sync.aligned.m8n8.x4.shared.b16 {%0,%1,%2,%3}, [%4];"
                 : "=r"(r0), "=r"(r1), "=r"(r2), "=r"(r3) : "r"(addr));
}
__device__ __forceinline__ void mma16816(float* c, const unsigned* a, const unsigned* b) {
    asm volatile("mma.sync.aligned.m16n8k16.row.col.f32.bf16.bf16.f32 "
                 "{%0,%1,%2,%3}, {%4,%5,%6,%7}, {%8,%9}, {%0,%1,%2,%3};"
                 : "+f"(c[0]), "+f"(c[1]), "+f"(c[2]), "+f"(c[3])
                 : "r"(a[0]), "r"(a[1]), "r"(a[2]), "r"(a[3]), "r"(b[0]), "r"(b[1]));
}
__device__ __forceinline__ unsigned pk_bf16x2(float a, float b) {
    __nv_bfloat162 h = __floats2bfloat162_rn(a, b);
    return *(unsigned*)&h;
}
__device__ __forceinline__ unsigned fmono(float f) {
    unsigned u = __float_as_uint(f);
    return u ^ (((unsigned)((int)u >> 31)) | 0x80000000u);
}
__device__ __forceinline__ float funmono(unsigned m) {
    unsigned u = (m & 0x80000000u) ? (m ^ 0x80000000u) : ~m;
    return __uint_as_float(u);
}
__device__ __forceinline__ unsigned redux_max(unsigned v) {
    unsigned d;
    asm volatile("redux.sync.max.u32 %0, %1, 0xffffffff;" : "=r"(d) : "r"(v));
    return d;
}

// ================= convert fp32 -> bf16, 4 float4 per thread (MLP=4) =================
// Block covers 1024 float4s (256 thr x 4). x region: XBLK = X4/1024 blocks.
__global__ __launch_bounds__(256) void convert_kernel(
    const float4* __restrict__ x, const float4* __restrict__ wq,
    const float4* __restrict__ ka, const float4* __restrict__ kb,
    uint2* __restrict__ xb, uint2* __restrict__ wqb, uint2* __restrict__ kbb,
    int XBLK)
{
    const int W4 = (2 * D_KEY * D_MODEL) / 4;   // 65536
    const int K4 = (N_SUB * D_KEY) / 4;         // 8192
    const int tid = threadIdx.x;

    if (blockIdx.x < XBLK) {
        int base = blockIdx.x * 1024 + tid * 4;
        float4 v0 = __ldg(x + base + 0);
        float4 v1 = __ldg(x + base + 1);
        float4 v2 = __ldg(x + base + 2);
        float4 v3 = __ldg(x + base + 3);
        uint2 o0, o1, o2, o3;
        o0.x = pk_bf16x2(v0.x, v0.y); o0.y = pk_bf16x2(v0.z, v0.w);
        o1.x = pk_bf16x2(v1.x, v1.y); o1.y = pk_bf16x2(v1.z, v1.w);
        o2.x = pk_bf16x2(v2.x, v2.y); o2.y = pk_bf16x2(v2.z, v2.w);
        o3.x = pk_bf16x2(v3.x, v3.y); o3.y = pk_bf16x2(v3.z, v3.w);
        xb[base + 0] = o0; xb[base + 1] = o1; xb[base + 2] = o2; xb[base + 3] = o3;
    } else {
        // weights region: W4 + 2*K4 = 81920 float4s, 1024 per block -> 80 blocks
        int j = (blockIdx.x - XBLK) * 1024 + tid * 4;
        #pragma unroll
        for (int u = 0; u < 4; u++) {
            int i = j + u;
            float4 v; uint2 o;
            if (i < W4) {
                v = __ldg(wq + i);
                o.x = pk_bf16x2(v.x, v.y); o.y = pk_bf16x2(v.z, v.w);
                wqb[i] = o;
            } else if (i < W4 + K4) {
                v = __ldg(ka + (i - W4));
                o.x = pk_bf16x2(v.x, v.y); o.y = pk_bf16x2(v.z, v.w);
                kbb[i - W4] = o;
            } else if (i < W4 + 2 * K4) {
                v = __ldg(kb + (i - W4 - K4));
                o.x = pk_bf16x2(v.x, v.y); o.y = pk_bf16x2(v.z, v.w);
                kbb[K4 + (i - W4 - K4)] = o;
            }
        }
    }
}

// ================= fused GEMM1+GEMM2+half-top8, BK=64 (exact R14) =================
__global__ __launch_bounds__(256) void fused_gemm(
    const __nv_bfloat16* __restrict__ Xb,
    const __nv_bfloat16* __restrict__ Wqb,
    const __nv_bfloat16* __restrict__ Keys,
    unsigned* __restrict__ cand)
{
    extern __shared__ __align__(128) char dsm[];
    const unsigned sbase = smem_u32(dsm);
    const unsigned KB = sbase + 98304u;

    const int tid = threadIdx.x, lane = tid & 31, wid = tid >> 5;
    const int m0 = blockIdx.x * 128;
    const int z  = blockIdx.y;

    const __nv_bfloat16* __restrict__ Ab = Xb + (size_t)m0 * D_MODEL;
    const __nv_bfloat16* __restrict__ Bb = Wqb + (size_t)(z * D_KEY) * D_MODEL;
    const __nv_bfloat16* __restrict__ Kz = Keys + (size_t)z * N_SUB * D_KEY;

    const int wmA = (wid & 1) * 64;
    const int wnA = (wid >> 1) * 32;
    const int rowA = wmA + (lane & 15);
    const unsigned aSwz = (unsigned)rowA & 7;
    const unsigned aBase = (unsigned)rowA * 128;
    const unsigned aSel = lane >> 4;
    const int rowB = wnA + (lane & 7) + ((lane >> 4) << 3);
    const unsigned bSwz = (unsigned)rowB & 7;
    const unsigned bBase = (unsigned)rowB * 128;
    const unsigned bSel = (lane >> 3) & 1;

    float acc[4][4][4];
    #pragma unroll
    for (int mt = 0; mt < 4; mt++)
        #pragma unroll
        for (int nt = 0; nt < 4; nt++)
            #pragma unroll
            for (int e = 0; e < 4; e++) acc[mt][nt][e] = 0.f;

    auto fill = [&](int kt, int st) {
        const unsigned base = sbase + st * 32768u;
        const int kb = kt * 64;
        #pragma unroll
        for (int u = 0; u < 4; u++) {
            int idx = tid + u * 256;
            int r = idx >> 3, c = idx & 7;
            unsigned soff = (unsigned)r * 128 + (((unsigned)c ^ ((unsigned)r & 7)) << 4);
            cpa16(base + soff,          Ab + (size_t)r * D_MODEL + kb + c * 8);
            cpa16(base + 16384u + soff, Bb + (size_t)r * D_MODEL + kb + c * 8);
        }
    };

    fill(0, 0); cpcommit();
    fill(1, 1); cpcommit();
    #pragma unroll
    for (int i = 0; i < 16; i++) {
        int idx = tid + i * 256;
        int c2 = idx >> 11;
        int r  = (idx >> 3) & 255;
        int u  = idx & 7;
        cpa16(KB + (unsigned)c2 * 32768u + (unsigned)r * 128u +
                  ((((unsigned)u) ^ ((unsigned)r & 7)) << 4),
              Kz + (size_t)r * D_KEY + c2 * 64 + u * 8);
    }
    cpcommit();

    const int KT = 16;
    for (int kt = 0; kt < KT; kt++) {
        cpwait<2>();
        __syncthreads();
        int pf = kt + 2;
        if (pf < KT) fill(pf, pf % 3);
        cpcommit();

        const unsigned As = sbase + (kt % 3) * 32768u;
        const unsigned Bs = As + 16384u;
        #pragma unroll
        for (int kk = 0; kk < 4; kk++) {
            unsigned a[4][4];
            #pragma unroll
            for (int mt = 0; mt < 4; mt++)
                ldsm4(As + aBase + mt * 2048u + ((((unsigned)(kk * 2) + aSel) ^ aSwz) << 4),
                      a[mt][0], a[mt][1], a[mt][2], a[mt][3]);
            unsigned b[4][2];
            #pragma unroll
            for (int g = 0; g < 2; g++) {
                unsigned r0, r1, r2, r3;
                ldsm4(Bs + bBase + g * 2048u + ((((unsigned)(kk * 2) + bSel) ^ bSwz) << 4),
                      r0, r1, r2, r3);
                b[g * 2][0] = r0; b[g * 2][1] = r1;
                b[g * 2 + 1][0] = r2; b[g * 2 + 1][1] = r3;
            }
            #pragma unroll
            for (int mt = 0; mt < 4; mt++)
                #pragma unroll
                for (int nt = 0; nt < 4; nt++)
                    mma16816(acc[mt][nt], a[mt], b[nt]);
        }
        __syncthreads();
    }

    const int gid = lane >> 2;
    const int tg  = (lane & 3) * 2;
    #pragma unroll
    for (int mt = 0; mt < 4; mt++) {
        int r  = wmA + mt * 16 + gid;
        int r2 = r + 8;
        #pragma unroll
        for (int nt = 0; nt < 4; nt++) {
            int c = wnA + nt * 8 + tg;
            unsigned chunk = (unsigned)c >> 6, within = (unsigned)c & 63;
            unsigned u = within >> 3;
            unsigned byteoff0 = chunk * 16384u + (unsigned)r * 128u +
                                ((u ^ ((unsigned)r & 7)) << 4) + (within & 7) * 2;
            unsigned byteoff1 = chunk * 16384u + (unsigned)r2 * 128u +
                                ((u ^ ((unsigned)r2 & 7)) << 4) + (within & 7) * 2;
            *(unsigned*)(dsm + byteoff0) = pk_bf16x2(acc[mt][nt][0], acc[mt][nt][1]);
            *(unsigned*)(dsm + byteoff1) = pk_bf16x2(acc[mt][nt][2], acc[mt][nt][3]);
        }
    }
    cpwait<0>();
    __syncthreads();

    const int wmB = (wid & 1) * 64;
    const int wnB = (wid >> 1) * 64;
    const int rowA2 = wmB + (lane & 15);
    const unsigned aSwz2 = (unsigned)rowA2 & 7;
    const unsigned aBase2 = (unsigned)rowA2 * 128;
    const int rowB2 = wnB + (lane & 7) + ((lane >> 4) << 3);
    const unsigned bSwz2 = (unsigned)rowB2 & 7;
    const unsigned bBase2 = (unsigned)rowB2 * 128;

    float acc2[4][8][4];
    #pragma unroll
    for (int mt = 0; mt < 4; mt++)
        #pragma unroll
        for (int nt = 0; nt < 8; nt++)
            #pragma unroll
            for (int e = 0; e < 4; e++) acc2[mt][nt][e] = 0.f;

    #pragma unroll
    for (int k = 0; k < 2; k++) {
        const unsigned As = sbase + (unsigned)k * 16384u;
        const unsigned Bs = KB + (unsigned)k * 32768u;
        #pragma unroll
        for (int kk = 0; kk < 4; kk++) {
            unsigned a[4][4];
            #pragma unroll
            for (int mt = 0; mt < 4; mt++)
                ldsm4(As + aBase2 + mt * 2048u + ((((unsigned)(kk * 2) + aSel) ^ aSwz2) << 4),
                      a[mt][0], a[mt][1], a[mt][2], a[mt][3]);
            unsigned b[8][2];
            #pragma unroll
            for (int g = 0; g < 4; g++) {
                unsigned r0, r1, r2, r3;
                ldsm4(Bs + bBase2 + g * 2048u + ((((unsigned)(kk * 2) + bSel) ^ bSwz2) << 4),
                      r0, r1, r2, r3);
                b[g * 2][0] = r0; b[g * 2][1] = r1;
                b[g * 2 + 1][0] = r2; b[g * 2 + 1][1] = r3;
            }
            #pragma unroll
            for (int mt = 0; mt < 4; mt++)
                #pragma unroll
                for (int nt = 0; nt < 8; nt++)
                    mma16816(acc2[mt][nt], a[mt], b[nt]);
        }
    }

    __syncthreads();
    float* sc = (float*)dsm;
    #pragma unroll
    for (int mt = 0; mt < 4; mt++) {
        int r = wmB + mt * 16 + gid;
        #pragma unroll
        for (int nt = 0; nt < 8; nt++) {
            int col = wnB + nt * 8 + tg;
            *(float2*)&sc[(size_t)r * SC_LD + col]       = make_float2(acc2[mt][nt][0], acc2[mt][nt][1]);
            *(float2*)&sc[(size_t)(r + 8) * SC_LD + col] = make_float2(acc2[mt][nt][2], acc2[mt][nt][3]);
        }
    }
    __syncthreads();

    for (int j = 0; j < 8; j++) {
        const int r0 = wid * 16 + j;
        const int r1 = r0 + 8;
        unsigned k0[8], k1[8];
        #pragma unroll
        for (int s = 0; s < 8; s++) {
            unsigned tag = 255u - (unsigned)(s * 32 + lane);
            k0[s] = (fmono(sc[(size_t)r0 * SC_LD + s * 32 + lane]) & 0xFFFFFF00u) | tag;
            k1[s] = (fmono(sc[(size_t)r1 * SC_LD + s * 32 + lane]) & 0xFFFFFF00u) | tag;
        }
        unsigned my0 = 0u, my1 = 0u;
        #pragma unroll
        for (int it = 0; it < TOPK; it++) {
            unsigned l0 = k0[0], l1 = k1[0];
            #pragma unroll
            for (int s = 1; s < 8; s++) { l0 = max(l0, k0[s]); l1 = max(l1, k1[s]); }
            unsigned w0 = redux_max(l0);
            unsigned w1 = redux_max(l1);
            if (lane == it) { my0 = w0; my1 = w1; }
            #pragma unroll
            for (int s = 0; s < 8; s++) {
                if (k0[s] == w0) k0[s] = 0u;
                if (k1[s] == w1) k1[s] = 0u;
            }
        }
        if (lane < TOPK) {
            cand[(size_t)(m0 + r0) * 16 + z * 8 + lane] = my0;
            cand[(size_t)(m0 + r1) * 16 + z * 8 + lane] = my1;
        }
    }
}

// ================= gather + combine + softmax + gate + residual (exact R14) =================
__global__ __launch_bounds__(256) void gather_kernel(
    const unsigned* __restrict__ cand,
    const float* __restrict__ x, const float* __restrict__ values,
    const float* __restrict__ gate_w, const float* __restrict__ gate_b,
    float* __restrict__ out)
{
    const unsigned FULL = 0xffffffffu;
    const int t = blockIdx.x;
    const int tid = threadIdx.x;
    const int lane = tid & 31, wid = tid >> 5;

    const float4* xr = (const float4*)(x + (size_t)t * D_MODEL);
    float4 xv = xr[tid];
    float4 gv = ((const float4*)gate_w)[tid];

    const unsigned* c = cand + (size_t)t * 16;
    unsigned a0k = __ldg(c + (lane >> 3));
    unsigned a1k = __ldg(c + (lane >> 3) + 4);
    unsigned bk  = __ldg(c + 8 + (lane & 7));
    float bvf = funmono(bk & 0xFFFFFF00u);
    float c0 = funmono(a0k & 0xFFFFFF00u) + bvf;
    float c1 = funmono(a1k & 0xFFFFFF00u) + bvf;
    int ib  = 255 - (int)(bk & 255u);
    int idx0 = (255 - (int)(a0k & 255u)) * N_SUB + ib;
    int idx1 = (255 - (int)(a1k & 255u)) * N_SUB + ib;
    unsigned k0 = (fmono(c0) & ~63u) | (63u - (unsigned)lane);
    unsigned k1 = (fmono(c1) & ~63u) | (63u - (unsigned)(lane + 32));

    unsigned fkey = 0u; int fid = 0;
    #pragma unroll
    for (int it = 0; it < TOPK; it++) {
        unsigned loc = redux_max(max(k0, k1));
        unsigned pos = 63u - (loc & 63u);
        int src = (int)(pos & 31u);
        int widx = (pos < 32u) ? __shfl_sync(FULL, idx0, src)
                               : __shfl_sync(FULL, idx1, src);
        if (lane == it) { fkey = loc; fid = widx; }
        if (k0 == loc) k0 = 0u;
        if (k1 == loc) k1 = 0u;
    }

    float val = funmono(fkey & ~63u);
    float v0 = __shfl_sync(FULL, val, 0);
    float e = (lane < TOPK) ? expf(val - v0) : 0.f;
    float ssum = e;
    #pragma unroll
    for (int off = 4; off; off >>= 1) ssum += __shfl_xor_sync(FULL, ssum, off);
    float wk = e / ssum;

    float swv[TOPK]; int sidv[TOPK];
    #pragma unroll
    for (int k = 0; k < TOPK; k++) {
        swv[k]  = __shfl_sync(FULL, wk, k);
        sidv[k] = __shfl_sync(FULL, fid, k);
    }

    float p = xv.x * gv.x + xv.y * gv.y + xv.z * gv.z + xv.w * gv.w;
    #pragma unroll
    for (int off = 16; off; off >>= 1) p += __shfl_down_sync(FULL, p, off);
    __shared__ float red[8];
    if (lane == 0) red[wid] = p;

    float4 acc = make_float4(0.f, 0.f, 0.f, 0.f);
    #pragma unroll
    for (int k = 0; k < TOPK; k++) {
        const float4* vr = (const float4*)(values + (size_t)sidv[k] * D_MODEL);
        float4 vv = __ldg(vr + tid);
        float w = swv[k];
        acc.x += w * vv.x; acc.y += w * vv.y; acc.z += w * vv.z; acc.w += w * vv.w;
    }

    __syncthreads();
    float s = red[0] + red[1] + red[2] + red[3] + red[4] + red[5] + red[6] + red[7];
    const float g = 1.f / (1.f + expf(-(s + gate_b[0])));

    float4 o;
    o.x = xv.x + g * acc.x;
    o.y = xv.y + g * acc.y;
    o.z = xv.z + g * acc.z;
    o.w = xv.w + g * acc.w;
    ((float4*)(out + (size_t)t * D_MODEL))[tid] = o;
}

// ================= launch =================
extern "C" void kernel_launch(void* const* d_in, const int* in_sizes, int n_in,
                              void* d_out, int out_size)
{
    const float* x      = (const float*)d_in[0];
    const float* keys_a = (const float*)d_in[1];
    const float* keys_b = (const float*)d_in[2];
    const float* values = (const float*)d_in[3];
    const float* Wq     = (const float*)d_in[4];
    const float* gate_w = (const float*)d_in[5];
    const float* gate_b = (const float*)d_in[6];
    float* out = (float*)d_out;

    const int NT = in_sizes[0] / D_MODEL;   // 8192

    __nv_bfloat16 *xb, *wqb, *kbb;
    unsigned* cbuf;
    cudaGetSymbolAddress((void**)&xb,   g_xb);
    cudaGetSymbolAddress((void**)&wqb,  g_wqb);
    cudaGetSymbolAddress((void**)&kbb,  g_kb);
    cudaGetSymbolAddress((void**)&cbuf, g_cand);

    // 0) convert inputs to bf16 (4 float4 per thread, 1024 float4 per block)
    {
        int X4 = NT * D_MODEL / 4;          // 2097152
        int XBLK = X4 / 1024;               // 2048 blocks for x
        int WBLK = (81920 + 1023) / 1024;   // 80 blocks for weights/keys
        convert_kernel<<<XBLK + WBLK, 256>>>(
            (const float4*)x, (const float4*)Wq, (const float4*)keys_a, (const float4*)keys_b,
            (uint2*)xb, (uint2*)wqb, (uint2*)kbb, XBLK);
    }
    // 1) fused q-projection + scores + per-half top-8
    {
        const int dsm = 163840;
        cudaFuncSetAttribute(fused_gemm, cudaFuncAttributeMaxDynamicSharedMemorySize, dsm);
        dim3 grid(NT / 128, 2);
        fused_gemm<<<grid, 256, dsm>>>(xb, wqb, kbb, cbuf);
    }
    // 2) combine + softmax + gather + gate + residual
    gather_kernel<<<NT, 256>>>(cbuf, x, values, gate_w, gate_b, out);
}

// round 17
// speedup vs baseline: 1.0475x; 1.0475x over previous
#include <cuda_runtime.h>
#include <cuda_bf16.h>
#include <math.h>

#define D_MODEL 1024
#define D_KEY   128
#define N_SUB   256
#define TOPK    8
#define MAXNT   8192
#define SC_LD   260

// -------- scratch (device globals) --------
__device__ __align__(128) __nv_bfloat16 g_xb [MAXNT * D_MODEL];
__device__ __align__(128) __nv_bfloat16 g_wqb[2 * D_KEY * D_MODEL];
__device__ __align__(128) __nv_bfloat16 g_kb [2 * N_SUB * D_KEY];
__device__ __align__(128) unsigned g_cand[MAXNT * 16];

// ================= base-PTX helpers =================
__device__ __forceinline__ unsigned smem_u32(const void* p) {
    unsigned a;
    asm("{ .reg .u64 t; cvta.to.shared.u64 t, %1; cvt.u32.u64 %0, t; }" : "=r"(a) : "l"(p));
    return a;
}
__device__ __forceinline__ void cpa16(unsigned d, const void* s) {
    asm volatile("cp.async.cg.shared.global [%0], [%1], 16;" :: "r"(d), "l"(s));
}
__device__ __forceinline__ void cpcommit() { asm volatile("cp.async.commit_group;" ::: "memory"); }
template<int N> __device__ __forceinline__ void cpwait() {
    asm volatile("cp.async.wait_group %0;" :: "n"(N) : "memory");
}
__device__ __forceinline__ void ldsm4(unsigned addr, unsigned& r0, unsigned& r1,
                                      unsigned& r2, unsigned& r3) {
    asm volatile("ldmatrix.sync.aligned.m8n8.x4.shared.b16 {%0,%1,%2,%3}, [%4];"
                 : "=r"(r0), "=r"(r1), "=r"(r2), "=r"(r3) : "r"(addr));
}
__device__ __forceinline__ void mma16816(float* c, const unsigned* a, const unsigned* b) {
    asm volatile("mma.sync.aligned.m16n8k16.row.col.f32.bf16.bf16.f32 "
                 "{%0,%1,%2,%3}, {%4,%5,%6,%7}, {%8,%9}, {%0,%1,%2,%3};"
                 : "+f"(c[0]), "+f"(c[1]), "+f"(c[2]), "+f"(c[3])
                 : "r"(a[0]), "r"(a[1]), "r"(a[2]), "r"(a[3]), "r"(b[0]), "r"(b[1]));
}
__device__ __forceinline__ unsigned pk_bf16x2(float a, float b) {
    __nv_bfloat162 h = __floats2bfloat162_rn(a, b);
    return *(unsigned*)&h;
}
__device__ __forceinline__ unsigned fmono(float f) {
    unsigned u = __float_as_uint(f);
    return u ^ (((unsigned)((int)u >> 31)) | 0x80000000u);
}
__device__ __forceinline__ float funmono(unsigned m) {
    unsigned u = (m & 0x80000000u) ? (m ^ 0x80000000u) : ~m;
    return __uint_as_float(u);
}
__device__ __forceinline__ unsigned redux_max(unsigned v) {
    unsigned d;
    asm volatile("redux.sync.max.u32 %0, %1, 0xffffffff;" : "=r"(d) : "r"(v));
    return d;
}

// ================= convert fp32 -> bf16: coalesced, 4 independent loads/thread =================
// Block covers 1024 float4s; thread handles i = base + tid + u*256 (coalesced + MLP=4).
__global__ __launch_bounds__(256) void convert_kernel(
    const float4* __restrict__ x, const float4* __restrict__ wq,
    const float4* __restrict__ ka, const float4* __restrict__ kb,
    uint2* __restrict__ xb, uint2* __restrict__ wqb, uint2* __restrict__ kbb,
    int XBLK)
{
    const int W4 = (2 * D_KEY * D_MODEL) / 4;   // 65536
    const int K4 = (N_SUB * D_KEY) / 4;         // 8192
    const int tid = threadIdx.x;

    if (blockIdx.x < XBLK) {
        int base = blockIdx.x * 1024 + tid;
        float4 v0 = __ldg(x + base + 0 * 256);
        float4 v1 = __ldg(x + base + 1 * 256);
        float4 v2 = __ldg(x + base + 2 * 256);
        float4 v3 = __ldg(x + base + 3 * 256);
        uint2 o0, o1, o2, o3;
        o0.x = pk_bf16x2(v0.x, v0.y); o0.y = pk_bf16x2(v0.z, v0.w);
        o1.x = pk_bf16x2(v1.x, v1.y); o1.y = pk_bf16x2(v1.z, v1.w);
        o2.x = pk_bf16x2(v2.x, v2.y); o2.y = pk_bf16x2(v2.z, v2.w);
        o3.x = pk_bf16x2(v3.x, v3.y); o3.y = pk_bf16x2(v3.z, v3.w);
        xb[base + 0 * 256] = o0;
        xb[base + 1 * 256] = o1;
        xb[base + 2 * 256] = o2;
        xb[base + 3 * 256] = o3;
    } else {
        int base = (blockIdx.x - XBLK) * 1024 + tid;
        #pragma unroll
        for (int u = 0; u < 4; u++) {
            int i = base + u * 256;
            float4 v; uint2 o;
            if (i < W4) {
                v = __ldg(wq + i);
                o.x = pk_bf16x2(v.x, v.y); o.y = pk_bf16x2(v.z, v.w);
                wqb[i] = o;
            } else if (i < W4 + K4) {
                v = __ldg(ka + (i - W4));
                o.x = pk_bf16x2(v.x, v.y); o.y = pk_bf16x2(v.z, v.w);
                kbb[i - W4] = o;
            } else if (i < W4 + 2 * K4) {
                v = __ldg(kb + (i - W4 - K4));
                o.x = pk_bf16x2(v.x, v.y); o.y = pk_bf16x2(v.z, v.w);
                kbb[K4 + (i - W4 - K4)] = o;
            }
        }
    }
}

// ================= fused GEMM1+GEMM2+half-top8, BK=64 (exact R14) =================
__global__ __launch_bounds__(256) void fused_gemm(
    const __nv_bfloat16* __restrict__ Xb,
    const __nv_bfloat16* __restrict__ Wqb,
    const __nv_bfloat16* __restrict__ Keys,
    unsigned* __restrict__ cand)
{
    extern __shared__ __align__(128) char dsm[];
    const unsigned sbase = smem_u32(dsm);
    const unsigned KB = sbase + 98304u;

    const int tid = threadIdx.x, lane = tid & 31, wid = tid >> 5;
    const int m0 = blockIdx.x * 128;
    const int z  = blockIdx.y;

    const __nv_bfloat16* __restrict__ Ab = Xb + (size_t)m0 * D_MODEL;
    const __nv_bfloat16* __restrict__ Bb = Wqb + (size_t)(z * D_KEY) * D_MODEL;
    const __nv_bfloat16* __restrict__ Kz = Keys + (size_t)z * N_SUB * D_KEY;

    const int wmA = (wid & 1) * 64;
    const int wnA = (wid >> 1) * 32;
    const int rowA = wmA + (lane & 15);
    const unsigned aSwz = (unsigned)rowA & 7;
    const unsigned aBase = (unsigned)rowA * 128;
    const unsigned aSel = lane >> 4;
    const int rowB = wnA + (lane & 7) + ((lane >> 4) << 3);
    const unsigned bSwz = (unsigned)rowB & 7;
    const unsigned bBase = (unsigned)rowB * 128;
    const unsigned bSel = (lane >> 3) & 1;

    float acc[4][4][4];
    #pragma unroll
    for (int mt = 0; mt < 4; mt++)
        #pragma unroll
        for (int nt = 0; nt < 4; nt++)
            #pragma unroll
            for (int e = 0; e < 4; e++) acc[mt][nt][e] = 0.f;

    auto fill = [&](int kt, int st) {
        const unsigned base = sbase + st * 32768u;
        const int kb = kt * 64;
        #pragma unroll
        for (int u = 0; u < 4; u++) {
            int idx = tid + u * 256;
            int r = idx >> 3, c = idx & 7;
            unsigned soff = (unsigned)r * 128 + (((unsigned)c ^ ((unsigned)r & 7)) << 4);
            cpa16(base + soff,          Ab + (size_t)r * D_MODEL + kb + c * 8);
            cpa16(base + 16384u + soff, Bb + (size_t)r * D_MODEL + kb + c * 8);
        }
    };

    fill(0, 0); cpcommit();
    fill(1, 1); cpcommit();
    #pragma unroll
    for (int i = 0; i < 16; i++) {
        int idx = tid + i * 256;
        int c2 = idx >> 11;
        int r  = (idx >> 3) & 255;
        int u  = idx & 7;
        cpa16(KB + (unsigned)c2 * 32768u + (unsigned)r * 128u +
                  ((((unsigned)u) ^ ((unsigned)r & 7)) << 4),
              Kz + (size_t)r * D_KEY + c2 * 64 + u * 8);
    }
    cpcommit();

    const int KT = 16;
    for (int kt = 0; kt < KT; kt++) {
        cpwait<2>();
        __syncthreads();
        int pf = kt + 2;
        if (pf < KT) fill(pf, pf % 3);
        cpcommit();

        const unsigned As = sbase + (kt % 3) * 32768u;
        const unsigned Bs = As + 16384u;
        #pragma unroll
        for (int kk = 0; kk < 4; kk++) {
            unsigned a[4][4];
            #pragma unroll
            for (int mt = 0; mt < 4; mt++)
                ldsm4(As + aBase + mt * 2048u + ((((unsigned)(kk * 2) + aSel) ^ aSwz) << 4),
                      a[mt][0], a[mt][1], a[mt][2], a[mt][3]);
            unsigned b[4][2];
            #pragma unroll
            for (int g = 0; g < 2; g++) {
                unsigned r0, r1, r2, r3;
                ldsm4(Bs + bBase + g * 2048u + ((((unsigned)(kk * 2) + bSel) ^ bSwz) << 4),
                      r0, r1, r2, r3);
                b[g * 2][0] = r0; b[g * 2][1] = r1;
                b[g * 2 + 1][0] = r2; b[g * 2 + 1][1] = r3;
            }
            #pragma unroll
            for (int mt = 0; mt < 4; mt++)
                #pragma unroll
                for (int nt = 0; nt < 4; nt++)
                    mma16816(acc[mt][nt], a[mt], b[nt]);
        }
        __syncthreads();
    }

    const int gid = lane >> 2;
    const int tg  = (lane & 3) * 2;
    #pragma unroll
    for (int mt = 0; mt < 4; mt++) {
        int r  = wmA + mt * 16 + gid;
        int r2 = r + 8;
        #pragma unroll
        for (int nt = 0; nt < 4; nt++) {
            int c = wnA + nt * 8 + tg;
            unsigned chunk = (unsigned)c >> 6, within = (unsigned)c & 63;
            unsigned u = within >> 3;
            unsigned byteoff0 = chunk * 16384u + (unsigned)r * 128u +
                                ((u ^ ((unsigned)r & 7)) << 4) + (within & 7) * 2;
            unsigned byteoff1 = chunk * 16384u + (unsigned)r2 * 128u +
                                ((u ^ ((unsigned)r2 & 7)) << 4) + (within & 7) * 2;
            *(unsigned*)(dsm + byteoff0) = pk_bf16x2(acc[mt][nt][0], acc[mt][nt][1]);
            *(unsigned*)(dsm + byteoff1) = pk_bf16x2(acc[mt][nt][2], acc[mt][nt][3]);
        }
    }
    cpwait<0>();
    __syncthreads();

    const int wmB = (wid & 1) * 64;
    const int wnB = (wid >> 1) * 64;
    const int rowA2 = wmB + (lane & 15);
    const unsigned aSwz2 = (unsigned)rowA2 & 7;
    const unsigned aBase2 = (unsigned)rowA2 * 128;
    const int rowB2 = wnB + (lane & 7) + ((lane >> 4) << 3);
    const unsigned bSwz2 = (unsigned)rowB2 & 7;
    const unsigned bBase2 = (unsigned)rowB2 * 128;

    float acc2[4][8][4];
    #pragma unroll
    for (int mt = 0; mt < 4; mt++)
        #pragma unroll
        for (int nt = 0; nt < 8; nt++)
            #pragma unroll
            for (int e = 0; e < 4; e++) acc2[mt][nt][e] = 0.f;

    #pragma unroll
    for (int k = 0; k < 2; k++) {
        const unsigned As = sbase + (unsigned)k * 16384u;
        const unsigned Bs = KB + (unsigned)k * 32768u;
        #pragma unroll
        for (int kk = 0; kk < 4; kk++) {
            unsigned a[4][4];
            #pragma unroll
            for (int mt = 0; mt < 4; mt++)
                ldsm4(As + aBase2 + mt * 2048u + ((((unsigned)(kk * 2) + aSel) ^ aSwz2) << 4),
                      a[mt][0], a[mt][1], a[mt][2], a[mt][3]);
            unsigned b[8][2];
            #pragma unroll
            for (int g = 0; g < 4; g++) {
                unsigned r0, r1, r2, r3;
                ldsm4(Bs + bBase2 + g * 2048u + ((((unsigned)(kk * 2) + bSel) ^ bSwz2) << 4),
                      r0, r1, r2, r3);
                b[g * 2][0] = r0; b[g * 2][1] = r1;
                b[g * 2 + 1][0] = r2; b[g * 2 + 1][1] = r3;
            }
            #pragma unroll
            for (int mt = 0; mt < 4; mt++)
                #pragma unroll
                for (int nt = 0; nt < 8; nt++)
                    mma16816(acc2[mt][nt], a[mt], b[nt]);
        }
    }

    __syncthreads();
    float* sc = (float*)dsm;
    #pragma unroll
    for (int mt = 0; mt < 4; mt++) {
        int r = wmB + mt * 16 + gid;
        #pragma unroll
        for (int nt = 0; nt < 8; nt++) {
            int col = wnB + nt * 8 + tg;
            *(float2*)&sc[(size_t)r * SC_LD + col]       = make_float2(acc2[mt][nt][0], acc2[mt][nt][1]);
            *(float2*)&sc[(size_t)(r + 8) * SC_LD + col] = make_float2(acc2[mt][nt][2], acc2[mt][nt][3]);
        }
    }
    __syncthreads();

    for (int j = 0; j < 8; j++) {
        const int r0 = wid * 16 + j;
        const int r1 = r0 + 8;
        unsigned k0[8], k1[8];
        #pragma unroll
        for (int s = 0; s < 8; s++) {
            unsigned tag = 255u - (unsigned)(s * 32 + lane);
            k0[s] = (fmono(sc[(size_t)r0 * SC_LD + s * 32 + lane]) & 0xFFFFFF00u) | tag;
            k1[s] = (fmono(sc[(size_t)r1 * SC_LD + s * 32 + lane]) & 0xFFFFFF00u) | tag;
        }
        unsigned my0 = 0u, my1 = 0u;
        #pragma unroll
        for (int it = 0; it < TOPK; it++) {
            unsigned l0 = k0[0], l1 = k1[0];
            #pragma unroll
            for (int s = 1; s < 8; s++) { l0 = max(l0, k0[s]); l1 = max(l1, k1[s]); }
            unsigned w0 = redux_max(l0);
            unsigned w1 = redux_max(l1);
            if (lane == it) { my0 = w0; my1 = w1; }
            #pragma unroll
            for (int s = 0; s < 8; s++) {
                if (k0[s] == w0) k0[s] = 0u;
                if (k1[s] == w1) k1[s] = 0u;
            }
        }
        if (lane < TOPK) {
            cand[(size_t)(m0 + r0) * 16 + z * 8 + lane] = my0;
            cand[(size_t)(m0 + r1) * 16 + z * 8 + lane] = my1;
        }
    }
}

// ================= gather + combine + softmax + gate + residual (exact R14) =================
__global__ __launch_bounds__(256) void gather_kernel(
    const unsigned* __restrict__ cand,
    const float* __restrict__ x, const float* __restrict__ values,
    const float* __restrict__ gate_w, const float* __restrict__ gate_b,
    float* __restrict__ out)
{
    const unsigned FULL = 0xffffffffu;
    const int t = blockIdx.x;
    const int tid = threadIdx.x;
    const int lane = tid & 31, wid = tid >> 5;

    const float4* xr = (const float4*)(x + (size_t)t * D_MODEL);
    float4 xv = xr[tid];
    float4 gv = ((const float4*)gate_w)[tid];

    const unsigned* c = cand + (size_t)t * 16;
    unsigned a0k = __ldg(c + (lane >> 3));
    unsigned a1k = __ldg(c + (lane >> 3) + 4);
    unsigned bk  = __ldg(c + 8 + (lane & 7));
    float bvf = funmono(bk & 0xFFFFFF00u);
    float c0 = funmono(a0k & 0xFFFFFF00u) + bvf;
    float c1 = funmono(a1k & 0xFFFFFF00u) + bvf;
    int ib  = 255 - (int)(bk & 255u);
    int idx0 = (255 - (int)(a0k & 255u)) * N_SUB + ib;
    int idx1 = (255 - (int)(a1k & 255u)) * N_SUB + ib;
    unsigned k0 = (fmono(c0) & ~63u) | (63u - (unsigned)lane);
    unsigned k1 = (fmono(c1) & ~63u) | (63u - (unsigned)(lane + 32));

    unsigned fkey = 0u; int fid = 0;
    #pragma unroll
    for (int it = 0; it < TOPK; it++) {
        unsigned loc = redux_max(max(k0, k1));
        unsigned pos = 63u - (loc & 63u);
        int src = (int)(pos & 31u);
        int widx = (pos < 32u) ? __shfl_sync(FULL, idx0, src)
                               : __shfl_sync(FULL, idx1, src);
        if (lane == it) { fkey = loc; fid = widx; }
        if (k0 == loc) k0 = 0u;
        if (k1 == loc) k1 = 0u;
    }

    float val = funmono(fkey & ~63u);
    float v0 = __shfl_sync(FULL, val, 0);
    float e = (lane < TOPK) ? expf(val - v0) : 0.f;
    float ssum = e;
    #pragma unroll
    for (int off = 4; off; off >>= 1) ssum += __shfl_xor_sync(FULL, ssum, off);
    float wk = e / ssum;

    float swv[TOPK]; int sidv[TOPK];
    #pragma unroll
    for (int k = 0; k < TOPK; k++) {
        swv[k]  = __shfl_sync(FULL, wk, k);
        sidv[k] = __shfl_sync(FULL, fid, k);
    }

    float p = xv.x * gv.x + xv.y * gv.y + xv.z * gv.z + xv.w * gv.w;
    #pragma unroll
    for (int off = 16; off; off >>= 1) p += __shfl_down_sync(FULL, p, off);
    __shared__ float red[8];
    if (lane == 0) red[wid] = p;

    float4 acc = make_float4(0.f, 0.f, 0.f, 0.f);
    #pragma unroll
    for (int k = 0; k < TOPK; k++) {
        const float4* vr = (const float4*)(values + (size_t)sidv[k] * D_MODEL);
        float4 vv = __ldg(vr + tid);
        float w = swv[k];
        acc.x += w * vv.x; acc.y += w * vv.y; acc.z += w * vv.z; acc.w += w * vv.w;
    }

    __syncthreads();
    float s = red[0] + red[1] + red[2] + red[3] + red[4] + red[5] + red[6] + red[7];
    const float g = 1.f / (1.f + expf(-(s + gate_b[0])));

    float4 o;
    o.x = xv.x + g * acc.x;
    o.y = xv.y + g * acc.y;
    o.z = xv.z + g * acc.z;
    o.w = xv.w + g * acc.w;
    ((float4*)(out + (size_t)t * D_MODEL))[tid] = o;
}

// ================= launch =================
extern "C" void kernel_launch(void* const* d_in, const int* in_sizes, int n_in,
                              void* d_out, int out_size)
{
    const float* x      = (const float*)d_in[0];
    const float* keys_a = (const float*)d_in[1];
    const float* keys_b = (const float*)d_in[2];
    const float* values = (const float*)d_in[3];
    const float* Wq     = (const float*)d_in[4];
    const float* gate_w = (const float*)d_in[5];
    const float* gate_b = (const float*)d_in[6];
    float* out = (float*)d_out;

    const int NT = in_sizes[0] / D_MODEL;   // 8192

    __nv_bfloat16 *xb, *wqb, *kbb;
    unsigned* cbuf;
    cudaGetSymbolAddress((void**)&xb,   g_xb);
    cudaGetSymbolAddress((void**)&wqb,  g_wqb);
    cudaGetSymbolAddress((void**)&kbb,  g_kb);
    cudaGetSymbolAddress((void**)&cbuf, g_cand);

    // 0) convert inputs to bf16 (coalesced, 4 independent loads per thread)
    {
        int X4 = NT * D_MODEL / 4;          // 2097152
        int XBLK = X4 / 1024;               // 2048 blocks for x
        int WBLK = (81920 + 1023) / 1024;   // 80 blocks for weights/keys
        convert_kernel<<<XBLK + WBLK, 256>>>(
            (const float4*)x, (const float4*)Wq, (const float4*)keys_a, (const float4*)keys_b,
            (uint2*)xb, (uint2*)wqb, (uint2*)kbb, XBLK);
    }
    // 1) fused q-projection + scores + per-half top-8
    {
        const int dsm = 163840;
        cudaFuncSetAttribute(fused_gemm, cudaFuncAttributeMaxDynamicSharedMemorySize, dsm);
        dim3 grid(NT / 128, 2);
        fused_gemm<<<grid, 256, dsm>>>(xb, wqb, kbb, cbuf);
    }
    // 2) combine + softmax + gather + gate + residual
    gather_kernel<<<NT, 256>>>(cbuf, x, values, gate_w, gate_b, out);
}